// round 1
// baseline (speedup 1.0000x reference)
#include <cuda_runtime.h>

#define VOCAB 100
#define H 8
#define S 6
#define FF 16
#define NTAB (S * VOCAB)          // 600 (pos, id) combos
#define SEQ_PER_BLK 64
#define TPB (SEQ_PER_BLK * S)     // 384 threads
#define KV_STRIDE 100             // padded (6*16=96 -> 100) to kill bank conflicts

// Precomputed per-(pos,id) tables: x, q, k, v  (each 8 floats = 2 float4)
__device__ float4 g_Xtab[NTAB * 2];
__device__ float4 g_Qtab[NTAB * 2];
__device__ float4 g_Ktab[NTAB * 2];
__device__ float4 g_Vtab[NTAB * 2];

__global__ void precompute_kernel(
    const float* __restrict__ tok_emb, const float* __restrict__ pos_emb,
    const float* __restrict__ Wq, const float* __restrict__ bq,
    const float* __restrict__ Wk, const float* __restrict__ bk,
    const float* __restrict__ Wv, const float* __restrict__ bv)
{
    int idx = blockIdx.x * blockDim.x + threadIdx.x;
    if (idx >= NTAB) return;
    int pos = idx / VOCAB;
    int id  = idx % VOCAB;

    float x[8], q[8], k[8], v[8];
#pragma unroll
    for (int j = 0; j < 8; j++) x[j] = tok_emb[id * 8 + j] + pos_emb[pos * 8 + j];
#pragma unroll
    for (int i = 0; i < 8; i++) {
        float aq = bq[i], ak = bk[i], av = bv[i];
#pragma unroll
        for (int j = 0; j < 8; j++) {
            aq += x[j] * Wq[i * 8 + j];
            ak += x[j] * Wk[i * 8 + j];
            av += x[j] * Wv[i * 8 + j];
        }
        q[i] = aq; k[i] = ak; v[i] = av;
    }
    g_Xtab[idx * 2 + 0] = ((float4*)x)[0]; g_Xtab[idx * 2 + 1] = ((float4*)x)[1];
    g_Qtab[idx * 2 + 0] = ((float4*)q)[0]; g_Qtab[idx * 2 + 1] = ((float4*)q)[1];
    g_Ktab[idx * 2 + 0] = ((float4*)k)[0]; g_Ktab[idx * 2 + 1] = ((float4*)k)[1];
    g_Vtab[idx * 2 + 0] = ((float4*)v)[0]; g_Vtab[idx * 2 + 1] = ((float4*)v)[1];
}

// smem weight layout offsets
#define OFF_WO  0     // 64
#define OFF_BO  64    // 8
#define OFF_W1  72    // 128
#define OFF_B1  200   // 16
#define OFF_W2  216   // 128
#define OFF_B2  344   // 8
#define OFF_G1  352   // 8
#define OFF_BE1 360   // 8
#define OFF_G2  368   // 8
#define OFF_BE2 376   // 8
#define NWEIGHT 384

__global__ __launch_bounds__(TPB) void transformer_kernel(
    const int* __restrict__ ids,
    const float* __restrict__ Wo, const float* __restrict__ bo,
    const float* __restrict__ W1, const float* __restrict__ b1,
    const float* __restrict__ W2, const float* __restrict__ b2,
    const float* __restrict__ g1, const float* __restrict__ be1,
    const float* __restrict__ g2, const float* __restrict__ be2,
    float* __restrict__ out, int ntok)
{
    __shared__ float skv[SEQ_PER_BLK * KV_STRIDE];
    __shared__ float sW[NWEIGHT];

    int tid = threadIdx.x;
    // Stage all weights into shared memory (exactly TPB=384 = NWEIGHT entries)
    {
        float w;
        if      (tid < 64)  w = Wo[tid];
        else if (tid < 72)  w = bo[tid - 64];
        else if (tid < 200) w = W1[tid - 72];
        else if (tid < 216) w = b1[tid - 200];
        else if (tid < 344) w = W2[tid - 216];
        else if (tid < 352) w = b2[tid - 344];
        else if (tid < 360) w = g1[tid - 352];
        else if (tid < 368) w = be1[tid - 360];
        else if (tid < 376) w = g2[tid - 368];
        else                w = be2[tid - 376];
        sW[tid] = w;
    }

    int token = blockIdx.x * TPB + tid;
    bool valid = token < ntok;
    int pos  = token % S;
    int lseq = tid / S;
    int id   = valid ? ids[token] : 0;
    int tab  = (pos * VOCAB + id) * 2;

    // This token's k, v -> shared for the sequence's 6 threads
    {
        float4 k0 = g_Ktab[tab], k1 = g_Ktab[tab + 1];
        float4 v0 = g_Vtab[tab], v1 = g_Vtab[tab + 1];
        float* row = &skv[lseq * KV_STRIDE + pos * 16];
        ((float4*)row)[0] = k0;
        ((float4*)row)[1] = k1;
        ((float4*)row)[2] = v0;
        ((float4*)row)[3] = v1;
    }

    float q[8], x[8];
    {
        float4 q0 = g_Qtab[tab], q1 = g_Qtab[tab + 1];
        float4 x0 = g_Xtab[tab], x1 = g_Xtab[tab + 1];
        ((float4*)q)[0] = q0; ((float4*)q)[1] = q1;
        ((float4*)x)[0] = x0; ((float4*)x)[1] = x1;
    }

    __syncthreads();

    // ---- attention scores (2 heads, head_dim 4, scale 1/sqrt(4)=0.5) ----
    float p0[S], p1[S];
    const float* base = &skv[lseq * KV_STRIDE];
#pragma unroll
    for (int t = 0; t < S; t++) {
        const float* kt = base + t * 16;
        p0[t] = (q[0] * kt[0] + q[1] * kt[1] + q[2] * kt[2] + q[3] * kt[3]) * 0.5f;
        p1[t] = (q[4] * kt[4] + q[5] * kt[5] + q[6] * kt[6] + q[7] * kt[7]) * 0.5f;
    }
    // softmax
    float m0 = p0[0], m1 = p1[0];
#pragma unroll
    for (int t = 1; t < S; t++) { m0 = fmaxf(m0, p0[t]); m1 = fmaxf(m1, p1[t]); }
    float s0 = 0.f, s1 = 0.f;
#pragma unroll
    for (int t = 0; t < S; t++) {
        p0[t] = __expf(p0[t] - m0); s0 += p0[t];
        p1[t] = __expf(p1[t] - m1); s1 += p1[t];
    }
    float r0 = 1.0f / s0, r1 = 1.0f / s1;

    // ---- attn = probs @ v ----
    float attn[8];
#pragma unroll
    for (int i = 0; i < 8; i++) attn[i] = 0.f;
#pragma unroll
    for (int t = 0; t < S; t++) {
        const float* vt = base + t * 16 + 8;
#pragma unroll
        for (int d = 0; d < 4; d++) {
            attn[d]     += p0[t] * vt[d];
            attn[4 + d] += p1[t] * vt[4 + d];
        }
    }
#pragma unroll
    for (int d = 0; d < 4; d++) { attn[d] *= r0; attn[4 + d] *= r1; }

    // ---- output projection + residual ----
    float h[8];
#pragma unroll
    for (int i = 0; i < 8; i++) {
        float o = sW[OFF_BO + i];
#pragma unroll
        for (int j = 0; j < 8; j++) o += attn[j] * sW[OFF_WO + i * 8 + j];
        h[i] = x[i] + o;
    }

    // ---- LayerNorm 1 ----
    {
        float mu = 0.f;
#pragma unroll
        for (int i = 0; i < 8; i++) mu += h[i];
        mu *= 0.125f;
        float var = 0.f;
#pragma unroll
        for (int i = 0; i < 8; i++) { float d = h[i] - mu; var += d * d; }
        var *= 0.125f;
        float inv = rsqrtf(var + 1e-5f);
#pragma unroll
        for (int i = 0; i < 8; i++)
            h[i] = (h[i] - mu) * inv * sW[OFF_G1 + i] + sW[OFF_BE1 + i];
    }

    // ---- FFN: gelu(h@W1.T + b1) @ W2.T + b2 ----
    float acc[8];
#pragma unroll
    for (int i = 0; i < 8; i++) acc[i] = sW[OFF_B2 + i];
#pragma unroll
    for (int j = 0; j < FF; j++) {
        float a = sW[OFF_B1 + j];
#pragma unroll
        for (int i = 0; i < 8; i++) a += h[i] * sW[OFF_W1 + j * 8 + i];
        float g = 0.5f * a * (1.0f + erff(a * 0.70710678118654752f));
#pragma unroll
        for (int i = 0; i < 8; i++) acc[i] += g * sW[OFF_W2 + i * 16 + j];
    }

    // ---- residual + LayerNorm 2 ----
#pragma unroll
    for (int i = 0; i < 8; i++) acc[i] += h[i];
    {
        float mu = 0.f;
#pragma unroll
        for (int i = 0; i < 8; i++) mu += acc[i];
        mu *= 0.125f;
        float var = 0.f;
#pragma unroll
        for (int i = 0; i < 8; i++) { float d = acc[i] - mu; var += d * d; }
        var *= 0.125f;
        float inv = rsqrtf(var + 1e-5f);
        float y[8];
#pragma unroll
        for (int i = 0; i < 8; i++)
            y[i] = (acc[i] - mu) * inv * sW[OFF_G2 + i] + sW[OFF_BE2 + i];

        if (valid) {
            float4* o4 = (float4*)(out + (size_t)token * 8);
            o4[0] = ((float4*)y)[0];
            o4[1] = ((float4*)y)[1];
        }
    }
}

extern "C" void kernel_launch(void* const* d_in, const int* in_sizes, int n_in,
                              void* d_out, int out_size)
{
    const int*   ids     = (const int*)d_in[0];
    const float* tok_emb = (const float*)d_in[1];
    const float* pos_emb = (const float*)d_in[2];
    const float* Wq = (const float*)d_in[3];
    const float* bq = (const float*)d_in[4];
    const float* Wk = (const float*)d_in[5];
    const float* bk = (const float*)d_in[6];
    const float* Wv = (const float*)d_in[7];
    const float* bv = (const float*)d_in[8];
    const float* Wo = (const float*)d_in[9];
    const float* bo = (const float*)d_in[10];
    const float* W1 = (const float*)d_in[11];
    const float* b1 = (const float*)d_in[12];
    const float* W2 = (const float*)d_in[13];
    const float* b2 = (const float*)d_in[14];
    const float* g1 = (const float*)d_in[15];
    const float* be1 = (const float*)d_in[16];
    const float* g2 = (const float*)d_in[17];
    const float* be2 = (const float*)d_in[18];
    float* out = (float*)d_out;

    int ntok = in_sizes[0];  // B * S

    precompute_kernel<<<(NTAB + 127) / 128, 128>>>(tok_emb, pos_emb, Wq, bq, Wk, bk, Wv, bv);

    int grid = (ntok + TPB - 1) / TPB;
    transformer_kernel<<<grid, TPB>>>(ids, Wo, bo, W1, b1, W2, b2,
                                      g1, be1, g2, be2, out, ntok);
}